// round 5
// baseline (speedup 1.0000x reference)
#include <cuda_runtime.h>
#include <cuda_bf16.h>

// WaveletTransform: 3-level low-pass pyramid on x[8,32,512,512] fp32.
// out = x, except per-channel:
//   out[0:256,0:256] = down2x(conv3x3(x[0:512,0:512]))        (level 0)
//   out[0:128,0:128] = down2x(conv3x3(level0 result[0:256]^2)) (level 1)
//   out[0: 64,0: 64] = down2x(conv3x3(level1 result[0:128]^2)) (level 2)
// conv kernel = outer([.25,.5,.25],[.25,.5,.25]), zero-padded 'same',
// downsample takes even indices (center 2i,2j -> taps 2i-1..2i+1).
//
// R2: conv paths use 2x aligned LDG.128 per row + __shfl_up for left halo.
// R3: K1 8 rows / 256 threads per CTA, streaming stores on copy region.
// R4: levels 1+2 fused into one smem-resident CTA-per-channel kernel.
// R5: channels chunked 4x64; K23(c) forked onto a side stream after K1(c),
//     overlapping with K1(c+1) (K23 was latency-bound at 45% DRAM while K1
//     saturates DRAM -> hide K23 and catch K1's conv stores in L2).

#define BC_TOTAL (8 * 32)
#define NCHUNK   4
#define CHUNK    (BC_TOTAL / NCHUNK)   // 64 channels per chunk
#define H0 512
#define W0C 512

#define L1_STRIDE 132                       // 128 + 4 floats pad
#define K23_SMEM (128 * L1_STRIDE * 4)      // 67584 bytes

__device__ __forceinline__ float hfilt(float a, float b, float c) {
    return 0.25f * a + 0.5f * b + 0.25f * c;
}

// ---------------------------------------------------------------------------
// K1: fused identity copy + level-0 conv-down into top-left 256^2.
// grid (1,64,CHUNK), block 256. sub = tid>>7 selects a 4-row group; each
// thread owns column group j4 (float4) across 4 consecutive rows.
// ---------------------------------------------------------------------------
__global__ void __launch_bounds__(256) k1_copy_down0(
    const float* __restrict__ x, float* __restrict__ out, int bc_off)
{
    const int j4   = threadIdx.x & 127;          // 0..127 (col/4)
    const int sub  = threadIdx.x >> 7;           // 0..1
    const int base = blockIdx.y * 8 + sub * 4;   // first of 4 rows
    const int bc   = blockIdx.z + bc_off;

    const float* xp = x   + (size_t)bc * H0 * W0C;
    float*       op = out + (size_t)bc * H0 * W0C;

    if (base < 256 && j4 < 64) {
        #pragma unroll
        for (int it = 0; it < 4; it++) {
            const int i  = base + it;
            const int r0 = 2 * i - 1;            // -1 only when i==0
            float acc0 = 0.f, acc1 = 0.f, acc2 = 0.f, acc3 = 0.f;
            #pragma unroll
            for (int a = 0; a < 3; a++) {
                const int r = r0 + a;            // <= 511
                if (r < 0) continue;             // warp-uniform
                const float wr = (a == 1) ? 0.5f : 0.25f;
                const float* row = xp + (size_t)r * W0C;
                const float4* rv = reinterpret_cast<const float4*>(row) + 2 * j4;
                float4 p0 = rv[0];
                float4 p1 = rv[1];
                float left = __shfl_up_sync(0xFFFFFFFFu, p1.w, 1);
                if ((j4 & 31) == 0)
                    left = (j4 == 0) ? 0.f : row[8 * j4 - 1];
                acc0 += wr * hfilt(left, p0.x, p0.y);
                acc1 += wr * hfilt(p0.y, p0.z, p0.w);
                acc2 += wr * hfilt(p0.w, p1.x, p1.y);
                acc3 += wr * hfilt(p1.y, p1.z, p1.w);
            }
            *reinterpret_cast<float4*>(op + (size_t)i * W0C + 4 * j4) =
                make_float4(acc0, acc1, acc2, acc3);
        }
    } else {
        float4 v[4];
        #pragma unroll
        for (int it = 0; it < 4; it++)
            v[it] = *(reinterpret_cast<const float4*>(
                          xp + (size_t)(base + it) * W0C) + j4);
        #pragma unroll
        for (int it = 0; it < 4; it++)
            __stcs(reinterpret_cast<float4*>(
                       op + (size_t)(base + it) * W0C) + j4, v[it]);
    }
}

// ---------------------------------------------------------------------------
// K23: fused levels 1+2. One CTA per channel, 1024 threads, level-1 in smem.
// Phase 1: level-1 conv from out[0:256]^2 (stride 512) -> smem [128][132].
// Phase 2: out[0:128]^2 <- inner 64^2 conv of smem, remainder smem copy.
// ---------------------------------------------------------------------------
__global__ void __launch_bounds__(1024) k23_fused(float* __restrict__ out,
                                                  int bc_off)
{
    extern __shared__ float l1[];               // [128][L1_STRIDE]
    const int lane = threadIdx.x & 31;
    const int wy   = threadIdx.x >> 5;          // 0..31
    const int bc   = blockIdx.x + bc_off;

    float* op = out + (size_t)bc * H0 * W0C;

    // Phase 1: level-1 conv (reads level-0 result written by K1)
    #pragma unroll
    for (int it = 0; it < 4; it++) {
        const int i  = wy * 4 + it;             // 0..127
        const int r0 = 2 * i - 1;
        float acc0 = 0.f, acc1 = 0.f, acc2 = 0.f, acc3 = 0.f;
        #pragma unroll
        for (int a = 0; a < 3; a++) {
            const int r = r0 + a;               // <= 255
            if (r < 0) continue;                // warp-uniform
            const float wr = (a == 1) ? 0.5f : 0.25f;
            const float* row = op + (size_t)r * W0C;
            const float4* rv = reinterpret_cast<const float4*>(row) + 2 * lane;
            float4 p0 = rv[0];
            float4 p1 = rv[1];
            float left = __shfl_up_sync(0xFFFFFFFFu, p1.w, 1);
            if (lane == 0) left = 0.f;
            acc0 += wr * hfilt(left, p0.x, p0.y);
            acc1 += wr * hfilt(p0.y, p0.z, p0.w);
            acc2 += wr * hfilt(p0.w, p1.x, p1.y);
            acc3 += wr * hfilt(p1.y, p1.z, p1.w);
        }
        *reinterpret_cast<float4*>(&l1[i * L1_STRIDE + 4 * lane]) =
            make_float4(acc0, acc1, acc2, acc3);
    }
    __syncthreads();

    // Phase 2: level-2 conv (inner 64^2) + copy, write out[0:128]^2
    #pragma unroll
    for (int it = 0; it < 4; it++) {
        const int i = wy * 4 + it;              // 0..127
        float4 val;
        if (i < 64 && lane < 16) {
            const int r0 = 2 * i - 1;
            float acc0 = 0.f, acc1 = 0.f, acc2 = 0.f, acc3 = 0.f;
            #pragma unroll
            for (int a = 0; a < 3; a++) {
                const int r = r0 + a;           // <= 127
                if (r < 0) continue;
                const float wr = (a == 1) ? 0.5f : 0.25f;
                const float* row = &l1[r * L1_STRIDE];
                float4 p0 = *reinterpret_cast<const float4*>(row + 8 * lane);
                float4 p1 = *reinterpret_cast<const float4*>(row + 8 * lane + 4);
                float left = __shfl_up_sync(0x0000FFFFu, p1.w, 1);
                if (lane == 0) left = 0.f;
                acc0 += wr * hfilt(left, p0.x, p0.y);
                acc1 += wr * hfilt(p0.y, p0.z, p0.w);
                acc2 += wr * hfilt(p0.w, p1.x, p1.y);
                acc3 += wr * hfilt(p1.y, p1.z, p1.w);
            }
            val = make_float4(acc0, acc1, acc2, acc3);
        } else {
            val = *reinterpret_cast<const float4*>(&l1[i * L1_STRIDE + 4 * lane]);
        }
        *reinterpret_cast<float4*>(op + (size_t)i * W0C + 4 * lane) = val;
    }
}

extern "C" void kernel_launch(void* const* d_in, const int* in_sizes, int n_in,
                              void* d_out, int out_size)
{
    (void)in_sizes; (void)n_in; (void)out_size;
    const float* x = (const float*)d_in[0];
    float* out = (float*)d_out;

    static cudaStream_t s_side = nullptr;
    static cudaEvent_t  s_ev[NCHUNK];
    static cudaEvent_t  s_join;
    if (!s_side) {
        cudaFuncSetAttribute(k23_fused,
                             cudaFuncAttributeMaxDynamicSharedMemorySize,
                             K23_SMEM);
        cudaStreamCreateWithFlags(&s_side, cudaStreamNonBlocking);
        for (int c = 0; c < NCHUNK; c++)
            cudaEventCreateWithFlags(&s_ev[c], cudaEventDisableTiming);
        cudaEventCreateWithFlags(&s_join, cudaEventDisableTiming);
    }

    for (int c = 0; c < NCHUNK; c++) {
        const int off = c * CHUNK;
        k1_copy_down0<<<dim3(1, 64, CHUNK), dim3(256)>>>(x, out, off);
        cudaEventRecord(s_ev[c], 0);
        cudaStreamWaitEvent(s_side, s_ev[c], 0);
        k23_fused<<<dim3(CHUNK), dim3(1024), K23_SMEM, s_side>>>(out, off);
    }
    // join side stream back into the captured origin stream
    cudaEventRecord(s_join, s_side);
    cudaStreamWaitEvent(0, s_join, 0);
}